// round 14
// baseline (speedup 1.0000x reference)
#include <cuda_runtime.h>
#include <math.h>
#include <stdint.h>

#define VOCAB 32000
#define EMB 256
#define HID 256
#define BATCH 64
#define SEQT 2048

// Scratch: V[v][j] = sum_e emb[v][e]*W_ih[e][j] + b_ih[j] + b_hh[j]  (32 MB, L2-resident)
__device__ float g_V[VOCAB * HID];

// ---------------------------------------------------------------------------
// f32x2 packed helpers (PTX-only; ptxas won't auto-fuse)
// ---------------------------------------------------------------------------
__device__ __forceinline__ unsigned long long pack2(float lo, float hi) {
    unsigned long long r;
    asm("mov.b64 %0, {%1, %2};" : "=l"(r) : "f"(lo), "f"(hi));
    return r;
}
__device__ __forceinline__ void fma2(unsigned long long& acc,
                                     unsigned long long a, unsigned long long b) {
    asm("fma.rn.f32x2 %0, %1, %2, %0;" : "+l"(acc) : "l"(a), "l"(b));
}
__device__ __forceinline__ unsigned long long add2(unsigned long long a,
                                                   unsigned long long b) {
    unsigned long long r;
    asm("add.rn.f32x2 %0, %1, %2;" : "=l"(r) : "l"(a), "l"(b));
    return r;
}
__device__ __forceinline__ void unpack2(unsigned long long v, float& lo, float& hi) {
    asm("mov.b64 {%0, %1}, %2;" : "=f"(lo), "=f"(hi) : "l"(v));
}
__device__ __forceinline__ unsigned long long shfl_bfly_u64(unsigned long long v,
                                                            int mask) {
    uint32_t lo = (uint32_t)v, hi = (uint32_t)(v >> 32);
    lo = __shfl_xor_sync(0xffffffffu, lo, mask);
    hi = __shfl_xor_sync(0xffffffffu, hi, mask);
    return ((unsigned long long)hi << 32) | lo;
}

// ---------------------------------------------------------------------------
// Kernel 1: vocab projection GEMM  [32000,256] x [256,256] + bias  (f32x2)
// ---------------------------------------------------------------------------
__global__ void __launch_bounds__(256) vocab_proj_kernel(
    const float* __restrict__ emb, const float* __restrict__ W_ih,
    const float* __restrict__ b_ih, const float* __restrict__ b_hh)
{
    __shared__ float As_T[32][68];
    const int row0 = blockIdx.x * 64;
    const int j = threadIdx.x;

    const float bias = b_ih[j] + b_hh[j];

    unsigned long long acc[32];
#pragma unroll
    for (int p = 0; p < 32; p++) acc[p] = 0ull;

#pragma unroll 1
    for (int k0 = 0; k0 < EMB; k0 += 32) {
        __syncthreads();
#pragma unroll
        for (int it = 0; it < 8; it++) {
            int idx = it * 256 + threadIdx.x;
            int r  = idx >> 5;
            int kk = idx & 31;
            As_T[kk][r] = emb[(size_t)(row0 + r) * EMB + (k0 + kk)];
        }
        __syncthreads();

        float wt[32];
#pragma unroll
        for (int kk = 0; kk < 32; kk++)
            wt[kk] = W_ih[(size_t)(k0 + kk) * HID + j];

#pragma unroll
        for (int kk = 0; kk < 32; kk++) {
            unsigned long long ws = pack2(wt[kk], wt[kk]);
#pragma unroll
            for (int rp2 = 0; rp2 < 16; rp2++) {
                ulonglong2 av = *(const ulonglong2*)&As_T[kk][4 * rp2];
                fma2(acc[2 * rp2 + 0], av.x, ws);
                fma2(acc[2 * rp2 + 1], av.y, ws);
            }
        }
    }

#pragma unroll
    for (int p = 0; p < 32; p++) {
        float lo, hi;
        unpack2(acc[p], lo, hi);
        g_V[(size_t)(row0 + 2 * p + 0) * HID + j] = lo + bias;
        g_V[(size_t)(row0 + 2 * p + 1) * HID + j] = hi + bias;
    }
}

// ---------------------------------------------------------------------------
// Kernel 2: recurrence, SINGLE CTA per chain (R6 structure, FIXED W layout).
// 256 threads. Thread (warp w, lane l): kg = l&3 -> k in [64*kg, 64*kg+64),
// cl = l>>2; owns 4 columns c_i = 32w + 8i + cl; finalizes c_kg.
// W: per (col,i): k-rows [64kg, 64kg+52) in regs (104 f32x2 = 208 regs),
//    k-rows [64kg+52, 64kg+64) in SMEM scratch.
// *** W-scratch layout is TRANSPOSED: Ws[chunk][thread] so each LDS.128 has
//     16B-dense lane addresses -> ZERO bank conflicts (R6 had 4-way). ***
// h: 4 bank-staggered groups of 68 floats; cross-lane reduce via 2 bfly rounds.
// ---------------------------------------------------------------------------
#define KREGP 26   // k-pairs per column in registers (52 k's)
#define GSTR  68   // floats per h group (64 + 4 pad -> bank stagger)
#define NWCH  12   // W-scratch ulonglong2 chunks per thread (4 cols x 3)

__global__ void __launch_bounds__(256, 1)
rnn_kernel(const int* __restrict__ source, const float* __restrict__ W_hh,
           float* __restrict__ out)
{
    extern __shared__ __align__(16) char smraw[];
    ulonglong2* Ws  = (ulonglong2*)smraw;                    // [NWCH][256] u2 = 49152 B
    float* hbuf = (float*)(smraw + NWCH * 256 * 16);         // 2 * 4*68 floats
    int*   srcs = (int*)(hbuf + 2 * 4 * GSTR);               // 2048 ints

    const int t  = threadIdx.x;
    const int w  = t >> 5;
    const int l  = t & 31;
    const int kg = l & 3;
    const int cl = l >> 2;
    const int b  = blockIdx.x;
    const int kb = kg * 64;                 // lane's k-range base
    const int cown = 32 * w + 8 * kg + cl;  // column this lane finalizes

    for (int i = t; i < SEQT; i += 256) srcs[i] = source[b * SEQT + i];
    for (int i = t; i < 2 * 4 * GSTR; i += 256) hbuf[i] = 0.0f;

    // ---- Register-resident W: wr[i*26+kk] = (W[kb+2kk][c_i], W[kb+2kk+1][c_i])
    unsigned long long wr[4 * KREGP];
#pragma unroll
    for (int i = 0; i < 4; i++) {
        const int c = 32 * w + 8 * i + cl;
#pragma unroll
        for (int kk = 0; kk < KREGP; kk++)
            wr[i * KREGP + kk] = pack2(W_hh[(size_t)(kb + 2 * kk + 0) * HID + c],
                                       W_hh[(size_t)(kb + 2 * kk + 1) * HID + c]);
    }

    // ---- SMEM-resident W, TRANSPOSED layout: chunk q = i*3 + j holds
    // (col c_i, k's kb+52+4j .. kb+52+4j+3) as one ulonglong2, at Ws[q*256+t].
#pragma unroll
    for (int i = 0; i < 4; i++) {
        const int c = 32 * w + 8 * i + cl;
#pragma unroll
        for (int j = 0; j < 3; j++) {
            ulonglong2 v;
            v.x = pack2(W_hh[(size_t)(kb + 52 + 4 * j + 0) * HID + c],
                        W_hh[(size_t)(kb + 52 + 4 * j + 1) * HID + c]);
            v.y = pack2(W_hh[(size_t)(kb + 52 + 4 * j + 2) * HID + c],
                        W_hh[(size_t)(kb + 52 + 4 * j + 3) * HID + c]);
            Ws[(i * 3 + j) * 256 + t] = v;
        }
    }

    __syncthreads();

    const ulonglong2* ws_t = Ws + t;   // stride 256 u2 between chunks
    float hval = 0.0f;

#pragma unroll 1
    for (int step = 0; step < SEQT; step++) {
        const int cur = step & 1;

        // Prefetch x-projection for the finalized column (consumed at tail)
        const int idx = srcs[step];
        const float xv = g_V[(size_t)idx * HID + cown];

        // h group base for this lane's k-slice (bank-staggered groups)
        const float* hg = hbuf + cur * (4 * GSTR) + kg * GSTR;

        // Issue W-scratch loads first (12 conflict-free LDS.128, independent)
        ulonglong2 wq[NWCH];
#pragma unroll
        for (int q = 0; q < NWCH; q++) wq[q] = ws_t[q * 256];

        unsigned long long a0 = 0, a1 = 0, a2 = 0, a3 = 0;

        // Register-W part: k-pairs 0..25 of this lane's slice (broadcast h)
        const ulonglong2* hp2 = (const ulonglong2*)hg;
#pragma unroll
        for (int q = 0; q < 13; q++) {
            ulonglong2 hh = hp2[q];   // k-pairs 2q, 2q+1
            fma2(a0, hh.x, wr[0 * KREGP + 2 * q]); fma2(a0, hh.y, wr[0 * KREGP + 2 * q + 1]);
            fma2(a1, hh.x, wr[1 * KREGP + 2 * q]); fma2(a1, hh.y, wr[1 * KREGP + 2 * q + 1]);
            fma2(a2, hh.x, wr[2 * KREGP + 2 * q]); fma2(a2, hh.y, wr[2 * KREGP + 2 * q + 1]);
            fma2(a3, hh.x, wr[3 * KREGP + 2 * q]); fma2(a3, hh.y, wr[3 * KREGP + 2 * q + 1]);
        }

        // SMEM-W part: k's [kb+52, kb+64) = 3 h-ulonglong2, chunks i*3+j
        {
            const ulonglong2* hsm = (const ulonglong2*)(hg + 52);
#pragma unroll
            for (int j = 0; j < 3; j++) {
                ulonglong2 hh = hsm[j];
                fma2(a0, hh.x, wq[0 * 3 + j].x); fma2(a0, hh.y, wq[0 * 3 + j].y);
                fma2(a1, hh.x, wq[1 * 3 + j].x); fma2(a1, hh.y, wq[1 * 3 + j].y);
                fma2(a2, hh.x, wq[2 * 3 + j].x); fma2(a2, hh.y, wq[2 * 3 + j].y);
                fma2(a3, hh.x, wq[3 * 3 + j].x); fma2(a3, hh.y, wq[3 * 3 + j].y);
            }
        }

        // Per-column partials (lo+hi), packed; reduce across the 4 kg-lanes
        float s0lo, s0hi, s1lo, s1hi, s2lo, s2hi, s3lo, s3hi;
        unpack2(a0, s0lo, s0hi); unpack2(a1, s1lo, s1hi);
        unpack2(a2, s2lo, s2hi); unpack2(a3, s3lo, s3hi);
        unsigned long long p01 = pack2(s0lo + s0hi, s1lo + s1hi);
        unsigned long long p23 = pack2(s2lo + s2hi, s3lo + s3hi);

        p01 = add2(p01, shfl_bfly_u64(p01, 1));
        p23 = add2(p23, shfl_bfly_u64(p23, 1));
        p01 = add2(p01, shfl_bfly_u64(p01, 2));
        p23 = add2(p23, shfl_bfly_u64(p23, 2));

        float f0, f1, f2, f3;
        unpack2(p01, f0, f1);
        unpack2(p23, f2, f3);
        const float mine = (kg == 0) ? f0 : (kg == 1) ? f1 : (kg == 2) ? f2 : f3;

        const float pre = xv + mine;
        const float e = __expf(2.0f * pre);
        hval = 1.0f - __fdividef(2.0f, e + 1.0f);

        // Store h for next step: group (cown>>6), staggered layout
        hbuf[(cur ^ 1) * (4 * GSTR) + (cown >> 6) * GSTR + (cown & 63)] = hval;

        __syncthreads();
    }

    out[b * HID + cown] = hval;
}

// ---------------------------------------------------------------------------
extern "C" void kernel_launch(void* const* d_in, const int* in_sizes, int n_in,
                              void* d_out, int out_size)
{
    const int*   source    = (const int*)d_in[0];
    const float* embedding = (const float*)d_in[1];
    const float* W_ih      = (const float*)d_in[2];
    const float* W_hh      = (const float*)d_in[3];
    const float* b_ih      = (const float*)d_in[4];
    const float* b_hh      = (const float*)d_in[5];
    float* out = (float*)d_out;

    const int smem_bytes = NWCH * 256 * 16 + (2 * 4 * GSTR) * 4 + SEQT * 4;  // ~59.5 KB
    cudaFuncSetAttribute(rnn_kernel,
                         cudaFuncAttributeMaxDynamicSharedMemorySize,
                         smem_bytes);

    vocab_proj_kernel<<<VOCAB / 64, 256>>>(embedding, W_ih, b_ih, b_hh);
    rnn_kernel<<<BATCH, 256, smem_bytes>>>(source, W_hh, out);
}

// round 15
// speedup vs baseline: 1.4961x; 1.4961x over previous
#include <cuda_runtime.h>
#include <math.h>
#include <stdint.h>

#define VOCAB 32000
#define EMB 256
#define HID 256
#define BATCH 64
#define SEQT 2048

// Scratch: V[v][j] = sum_e emb[v][e]*W_ih[e][j] + b_ih[j] + b_hh[j]  (32 MB, L2-resident)
__device__ float g_V[VOCAB * HID];

// ---------------------------------------------------------------------------
// f32x2 packed helpers (PTX-only; ptxas won't auto-fuse)
// ---------------------------------------------------------------------------
__device__ __forceinline__ unsigned long long pack2(float lo, float hi) {
    unsigned long long r;
    asm("mov.b64 %0, {%1, %2};" : "=l"(r) : "f"(lo), "f"(hi));
    return r;
}
__device__ __forceinline__ void fma2(unsigned long long& acc,
                                     unsigned long long a, unsigned long long b) {
    asm("fma.rn.f32x2 %0, %1, %2, %0;" : "+l"(acc) : "l"(a), "l"(b));
}
__device__ __forceinline__ unsigned long long add2(unsigned long long a,
                                                   unsigned long long b) {
    unsigned long long r;
    asm("add.rn.f32x2 %0, %1, %2;" : "=l"(r) : "l"(a), "l"(b));
    return r;
}
__device__ __forceinline__ void unpack2(unsigned long long v, float& lo, float& hi) {
    asm("mov.b64 {%0, %1}, %2;" : "=f"(lo), "=f"(hi) : "l"(v));
}

// Cluster / mbarrier helpers
__device__ __forceinline__ uint32_t smem_u32(const void* p) {
    uint32_t a;
    asm("{ .reg .u64 t; cvta.to.shared.u64 t, %1; cvt.u32.u64 %0, t; }"
        : "=r"(a) : "l"(p));
    return a;
}
__device__ __forceinline__ uint32_t mapa_peer(uint32_t addr, uint32_t rank) {
    uint32_t r;
    asm("mapa.shared::cluster.u32 %0, %1, %2;" : "=r"(r) : "r"(addr), "r"(rank));
    return r;
}
__device__ __forceinline__ void mbar_init(uint32_t addr, uint32_t count) {
    asm volatile("mbarrier.init.shared.b64 [%0], %1;" :: "r"(addr), "r"(count) : "memory");
}
__device__ __forceinline__ void mbar_expect_tx(uint32_t addr, uint32_t bytes) {
    asm volatile("mbarrier.arrive.expect_tx.shared.b64 _, [%0], %1;"
                 :: "r"(addr), "r"(bytes) : "memory");
}
// Remote store fused with peer-mbar tx completion (data + signal in one op)
__device__ __forceinline__ void st_async_f32(uint32_t remote_addr, float v,
                                             uint32_t remote_mbar) {
    asm volatile(
        "st.async.shared::cluster.mbarrier::complete_tx::bytes.b32 [%0], %1, [%2];"
        :: "r"(remote_addr), "r"(__float_as_int(v)), "r"(remote_mbar) : "memory");
}
__device__ __forceinline__ void mbar_wait_parity(uint32_t addr, uint32_t parity) {
    uint32_t done;
    asm volatile(
        "{\n\t"
        ".reg .pred p;\n\t"
        "mbarrier.try_wait.parity.acquire.cluster.shared::cta.b64 p, [%1], %2;\n\t"
        "selp.b32 %0, 1, 0, p;\n\t"
        "}" : "=r"(done) : "r"(addr), "r"(parity) : "memory");
    if (!done) {
        asm volatile(
            "{\n\t"
            ".reg .pred P1;\n\t"
            "WL_%=:\n\t"
            "mbarrier.try_wait.parity.acquire.cluster.shared::cta.b64 P1, [%0], %1, 0x989680;\n\t"
            "@P1 bra.uni WD_%=;\n\t"
            "bra.uni WL_%=;\n\t"
            "WD_%=:\n\t"
            "}" :: "r"(addr), "r"(parity) : "memory");
    }
}
#define CLUSTER_SYNC() do { \
    asm volatile("barrier.cluster.arrive.aligned;" ::: "memory"); \
    asm volatile("barrier.cluster.wait.aligned;" ::: "memory"); \
} while (0)

// ---------------------------------------------------------------------------
// Kernel 1: vocab projection GEMM  [32000,256] x [256,256] + bias  (f32x2)
// ---------------------------------------------------------------------------
__global__ void __launch_bounds__(256) vocab_proj_kernel(
    const float* __restrict__ emb, const float* __restrict__ W_ih,
    const float* __restrict__ b_ih, const float* __restrict__ b_hh)
{
    __shared__ float As_T[32][68];
    const int row0 = blockIdx.x * 64;
    const int j = threadIdx.x;

    const float bias = b_ih[j] + b_hh[j];

    unsigned long long acc[32];
#pragma unroll
    for (int p = 0; p < 32; p++) acc[p] = 0ull;

#pragma unroll 1
    for (int k0 = 0; k0 < EMB; k0 += 32) {
        __syncthreads();
#pragma unroll
        for (int it = 0; it < 8; it++) {
            int idx = it * 256 + threadIdx.x;
            int r  = idx >> 5;
            int kk = idx & 31;
            As_T[kk][r] = emb[(size_t)(row0 + r) * EMB + (k0 + kk)];
        }
        __syncthreads();

        float wt[32];
#pragma unroll
        for (int kk = 0; kk < 32; kk++)
            wt[kk] = W_ih[(size_t)(k0 + kk) * HID + j];

#pragma unroll
        for (int kk = 0; kk < 32; kk++) {
            unsigned long long ws = pack2(wt[kk], wt[kk]);
#pragma unroll
            for (int rp2 = 0; rp2 < 16; rp2++) {
                ulonglong2 av = *(const ulonglong2*)&As_T[kk][4 * rp2];
                fma2(acc[2 * rp2 + 0], av.x, ws);
                fma2(acc[2 * rp2 + 1], av.y, ws);
            }
        }
    }

#pragma unroll
    for (int p = 0; p < 32; p++) {
        float lo, hi;
        unpack2(acc[p], lo, hi);
        g_V[(size_t)(row0 + 2 * p + 0) * HID + j] = lo + bias;
        g_V[(size_t)(row0 + 2 * p + 1) * HID + j] = hi + bias;
    }
}

// ---------------------------------------------------------------------------
// Kernel 2: recurrence. 2-CTA cluster per chain (R4 engine, non-blocking bars).
// Warp w: pair p = w&3 (cols p*32..p*32+31, one col/lane), kh = w>>2.
//  local warp  (kh == rank):   FMA over own-produced h half -> STS partial,
//      bar.arrive(pair) [non-blocking], bar.sync(end) [waits for finalizers].
//  remote warp (kh == rank^1): wait mbar, FMA over peer h half,
//      bar.sync(pair) [local already arrived -> ~20cyc], LDS partial, tanh,
//      STS h local + st.async h+signal to peer, bar.arrive(end) [non-blocking]
//      -> falls straight into the next step's mbar wait.
// Finalizers never read locally-produced h (only mbar-gated peer h), so they
// never need to block on the end barrier.
// ---------------------------------------------------------------------------
__global__ void __launch_bounds__(256, 1) __cluster_dims__(2, 1, 1)
rnn_kernel(const int* __restrict__ source, const float* __restrict__ W_hh,
           float* __restrict__ out)
{
    __shared__ float hs[2][256];
    __shared__ float partial[128];
    __shared__ int   src_s[SEQT];
    __shared__ __align__(8) unsigned long long mbar[2];

    const int t  = threadIdx.x;
    const int w  = t >> 5;
    const int l  = t & 31;
    const int p  = w & 3;         // pair id
    const int kh = w >> 2;        // k-half this warp multiplies
    const int col = p * 32 + l;   // local output column 0..127
    const int k0  = kh * 128;
    const int b   = blockIdx.x >> 1;

    uint32_t rank;
    asm("mov.u32 %0, %%cluster_ctarank;" : "=r"(rank));

    const int  jout      = (int)rank * 128 + col;   // global output column
    const bool is_remote = (kh != (int)rank);       // warp-uniform

    for (int i = t; i < SEQT; i += 256) src_s[i] = source[b * SEQT + i];

    // W_hh[k0..k0+127][jout] register-resident as 64 f32x2
    unsigned long long wreg[64];
#pragma unroll
    for (int i = 0; i < 64; i++)
        wreg[i] = pack2(W_hh[(size_t)(k0 + 2 * i + 0) * HID + jout],
                        W_hh[(size_t)(k0 + 2 * i + 1) * HID + jout]);

    hs[0][t] = 0.0f;
    hs[1][t] = 0.0f;
    if (t == 0) {
        mbar_init(smem_u32(&mbar[0]), 1);
        mbar_init(smem_u32(&mbar[1]), 1);
        mbar_expect_tx(smem_u32(&mbar[0]), 512);  // pre-arm phase 0 of both
        mbar_expect_tx(smem_u32(&mbar[1]), 512);
    }

    // Peer addresses
    uint32_t peer_h[2], peer_mbar[2], mbar_local[2];
    peer_h[0]    = mapa_peer(smem_u32(&hs[0][jout]), rank ^ 1u);
    peer_h[1]    = mapa_peer(smem_u32(&hs[1][jout]), rank ^ 1u);
    peer_mbar[0] = mapa_peer(smem_u32(&mbar[0]), rank ^ 1u);
    peer_mbar[1] = mapa_peer(smem_u32(&mbar[1]), rank ^ 1u);
    mbar_local[0] = smem_u32(&mbar[0]);
    mbar_local[1] = smem_u32(&mbar[1]);

    __syncthreads();
    CLUSTER_SYNC();  // mbar init + expect visible cluster-wide before any st.async

    float hval = 0.0f;

#pragma unroll 1
    for (int step = 0; step < SEQT; step++) {
        const int cur = step & 1;
        const int nxt = cur ^ 1;

        if (is_remote) {
            // Prefetch x-projection (LDS idx + L2 gather) — hides under wait+FMA
            float xv = g_V[(size_t)src_s[step] * HID + jout];

            if (step > 0) {
                mbar_wait_parity(mbar_local[cur], ((uint32_t)(step - 1) >> 1) & 1u);
                // Re-arm this mbar's next phase (filled 2 steps from now)
                if (p == 0 && l == 0) mbar_expect_tx(mbar_local[cur], 512);
            }

            const float* hp = &hs[cur][k0];   // peer half, mbar-gated
            unsigned long long a0 = 0, a1 = 0, a2 = 0, a3 = 0;
            unsigned long long b0 = 0, b1 = 0, b2 = 0, b3 = 0;
#pragma unroll
            for (int q = 0; q < 32; q += 4) {
                ulonglong2 h0 = *(const ulonglong2*)(hp + 4 * (q + 0));
                ulonglong2 h1 = *(const ulonglong2*)(hp + 4 * (q + 1));
                ulonglong2 h2 = *(const ulonglong2*)(hp + 4 * (q + 2));
                ulonglong2 h3 = *(const ulonglong2*)(hp + 4 * (q + 3));
                fma2(a0, h0.x, wreg[2 * q + 0]); fma2(b0, h0.y, wreg[2 * q + 1]);
                fma2(a1, h1.x, wreg[2 * q + 2]); fma2(b1, h1.y, wreg[2 * q + 3]);
                fma2(a2, h2.x, wreg[2 * q + 4]); fma2(b2, h2.y, wreg[2 * q + 5]);
                fma2(a3, h3.x, wreg[2 * q + 6]); fma2(b3, h3.y, wreg[2 * q + 7]);
            }
            unsigned long long s = add2(add2(add2(a0, a1), add2(a2, a3)),
                                        add2(add2(b0, b1), add2(b2, b3)));
            float lo, hi;
            unpack2(s, lo, hi);
            float pr = lo + hi;

            // Pair merge: local warp pre-arrived ~500cyc ago -> near-zero wait
            asm volatile("bar.sync %0, 64;" :: "r"(p + 1) : "memory");

            float pre = xv + pr + partial[col];
            float e = __expf(2.0f * pre);
            hval = 1.0f - __fdividef(2.0f, e + 1.0f);

            hs[nxt][jout] = hval;                 // local copy (for local warps)
            st_async_f32(peer_h[nxt], hval, peer_mbar[nxt]);  // data+signal fused

            // Non-blocking end-of-step: fall straight into next mbar wait
            asm volatile("bar.arrive 7, 256;" ::: "memory");
        } else {
            const float* hp = &hs[cur][k0];   // own half, ordered by end-bar
            unsigned long long a0 = 0, a1 = 0, a2 = 0, a3 = 0;
            unsigned long long b0 = 0, b1 = 0, b2 = 0, b3 = 0;
#pragma unroll
            for (int q = 0; q < 32; q += 4) {
                ulonglong2 h0 = *(const ulonglong2*)(hp + 4 * (q + 0));
                ulonglong2 h1 = *(const ulonglong2*)(hp + 4 * (q + 1));
                ulonglong2 h2 = *(const ulonglong2*)(hp + 4 * (q + 2));
                ulonglong2 h3 = *(const ulonglong2*)(hp + 4 * (q + 3));
                fma2(a0, h0.x, wreg[2 * q + 0]); fma2(b0, h0.y, wreg[2 * q + 1]);
                fma2(a1, h1.x, wreg[2 * q + 2]); fma2(b1, h1.y, wreg[2 * q + 3]);
                fma2(a2, h2.x, wreg[2 * q + 4]); fma2(b2, h2.y, wreg[2 * q + 5]);
                fma2(a3, h3.x, wreg[2 * q + 6]); fma2(b3, h3.y, wreg[2 * q + 7]);
            }
            unsigned long long s = add2(add2(add2(a0, a1), add2(a2, a3)),
                                        add2(add2(b0, b1), add2(b2, b3)));
            float lo, hi;
            unpack2(s, lo, hi);
            partial[col] = lo + hi;

            // Publish partial early (non-blocking), then wait for finalizers:
            // release of bar 7 orders finalizer hs[nxt] writes (and their
            // partial[] reads) before our next-step hs read / partial write.
            asm volatile("bar.arrive %0, 64;" :: "r"(p + 1) : "memory");
            asm volatile("bar.sync 7, 256;" ::: "memory");
        }
    }

    if (is_remote) out[b * HID + jout] = hval;

    CLUSTER_SYNC();  // keep peer SMEM alive for in-flight final st.asyncs
}

// ---------------------------------------------------------------------------
extern "C" void kernel_launch(void* const* d_in, const int* in_sizes, int n_in,
                              void* d_out, int out_size)
{
    const int*   source    = (const int*)d_in[0];
    const float* embedding = (const float*)d_in[1];
    const float* W_ih      = (const float*)d_in[2];
    const float* W_hh      = (const float*)d_in[3];
    const float* b_ih      = (const float*)d_in[4];
    const float* b_hh      = (const float*)d_in[5];
    float* out = (float*)d_out;

    vocab_proj_kernel<<<VOCAB / 64, 256>>>(embedding, W_ih, b_ih, b_hh);
    rnn_kernel<<<BATCH * 2, 256>>>(source, W_hh, out);
}